// round 1
// baseline (speedup 1.0000x reference)
#include <cuda_runtime.h>
#include <cstdint>

#define NN 100000
#define EE 1250000
#define HH 128
#define DD 64
#define EPSBN 1e-5f
#define SCAN_B 1024
#define NB_SCAN ((NN + SCAN_B - 1) / SCAN_B)   // 98

// ---------------- static device scratch (no runtime allocation allowed) ----------------
__device__ int g_deg[NN];
__device__ int g_rowptr[NN + 1];
__device__ int g_fill[NN];
__device__ int g_csr[EE];
__device__ int g_bsums[NB_SCAN];
__device__ __align__(16) float g_neigh[(size_t)NN * HH];
__device__ __align__(16) float g_h0[(size_t)NN * HH];
__device__ __align__(16) float g_h1[(size_t)NN * HH];
__device__ __align__(16) float g_colsum[HH];
__device__ __align__(16) float g_colsq[HH];
__device__ __align__(16) float g_scale[HH];
__device__ __align__(16) float g_shift[HH];

// ---------------- init: zero counters + BN accumulators ----------------
__global__ void k_init() {
    int i = blockIdx.x * blockDim.x + threadIdx.x;
    if (i < NN) { g_deg[i] = 0; g_fill[i] = 0; }
    if (i < HH) { g_colsum[i] = 0.f; g_colsq[i] = 0.f; }
}

// ---------------- CSR build ----------------
__global__ void k_hist(const int* __restrict__ dst) {
    int e = blockIdx.x * blockDim.x + threadIdx.x;
    if (e < EE) atomicAdd(&g_deg[dst[e]], 1);
}

__global__ void k_scan1() {
    __shared__ int s[SCAN_B];
    int tid = threadIdx.x;
    int i = blockIdx.x * SCAN_B + tid;
    int v = (i < NN) ? g_deg[i] : 0;
    s[tid] = v;
    __syncthreads();
    for (int off = 1; off < SCAN_B; off <<= 1) {
        int t = (tid >= off) ? s[tid - off] : 0;
        __syncthreads();
        s[tid] += t;
        __syncthreads();
    }
    if (i < NN) g_rowptr[i] = s[tid] - v;           // exclusive
    if (tid == SCAN_B - 1) g_bsums[blockIdx.x] = s[tid];
}

__global__ void k_scan2() {
    __shared__ int s[128];
    int tid = threadIdx.x;
    int v = (tid < NB_SCAN) ? g_bsums[tid] : 0;
    s[tid] = v;
    __syncthreads();
    for (int off = 1; off < 128; off <<= 1) {
        int t = (tid >= off) ? s[tid - off] : 0;
        __syncthreads();
        s[tid] += t;
        __syncthreads();
    }
    if (tid < NB_SCAN) g_bsums[tid] = s[tid] - v;   // exclusive over block sums
    if (tid == 127) g_rowptr[NN] = s[127];          // total = E
}

__global__ void k_scan3() {
    int i = blockIdx.x * SCAN_B + threadIdx.x;
    if (i < NN) g_rowptr[i] += g_bsums[blockIdx.x];
}

__global__ void k_fill(const int* __restrict__ src, const int* __restrict__ dst) {
    int e = blockIdx.x * blockDim.x + threadIdx.x;
    if (e < EE) {
        int d = dst[e];
        int p = atomicAdd(&g_fill[d], 1);
        g_csr[g_rowptr[d] + p] = src[e];
    }
}

// ---------------- mean aggregation: one warp per node, atomic-free ----------------
template <int DIN>
__global__ void k_agg(const float* __restrict__ xin) {
    int gw = (blockIdx.x * blockDim.x + threadIdx.x) >> 5;
    int lane = threadIdx.x & 31;
    if (gw >= NN) return;
    int beg = g_rowptr[gw], end = g_rowptr[gw + 1];
    const int R = DIN / 32;
    float acc[R];
#pragma unroll
    for (int j = 0; j < R; j++) acc[j] = 0.f;
#pragma unroll 2
    for (int e = beg; e < end; e++) {
        int s = g_csr[e];
        const float* row = xin + (size_t)s * DIN;
#pragma unroll
        for (int j = 0; j < R; j++) acc[j] += __ldg(row + lane + 32 * j);
    }
    float inv = (end > beg) ? 1.0f / (float)(end - beg) : 0.f;
    float* o = g_neigh + (size_t)gw * DIN;
#pragma unroll
    for (int j = 0; j < R; j++) o[lane + 32 * j] = acc[j] * inv;
}

// ---------------- fused dual-GEMM + bias + BN-stat partials ----------------
// h[n, :] = x[n,:] @ Wself + neigh[n,:] @ Wneigh + b   (H = 128 always)
// block: 256 threads = 8 warps, 64 nodes/block; thread: 8 nodes x 4 cols.
template <int DIN>
__launch_bounds__(256)
__global__ void k_gemm(const float* __restrict__ x,
                       const float* __restrict__ Wself,
                       const float* __restrict__ Wneigh,
                       const float* __restrict__ bself,
                       float* __restrict__ hout) {
    __shared__ float sX[64][20];     // +4 pad -> conflict-free f4-ish stores
    __shared__ float sNg[64][20];
    __shared__ float sWs[16][HH];
    __shared__ float sWn[16][HH];
    __shared__ float sred[8][HH];

    const int tid = threadIdx.x;
    const int warp = tid >> 5, lane = tid & 31;
    const int n0 = blockIdx.x * 64;

    float acc[8][4];
#pragma unroll
    for (int i = 0; i < 8; i++)
#pragma unroll
        for (int j = 0; j < 4; j++) acc[i][j] = 0.f;

    for (int k0 = 0; k0 < DIN; k0 += 16) {
        // load activation tiles: 64 nodes x 16 k  (1 float4 / thread / tensor)
        {
            int nl = tid >> 2;
            int ko = (tid & 3) * 4;
            int gn = min(n0 + nl, NN - 1);
            float4 xv = *(const float4*)(x + (size_t)gn * DIN + k0 + ko);
            float4 nv = *(const float4*)(g_neigh + (size_t)gn * DIN + k0 + ko);
            sX[nl][ko] = xv.x; sX[nl][ko + 1] = xv.y; sX[nl][ko + 2] = xv.z; sX[nl][ko + 3] = xv.w;
            sNg[nl][ko] = nv.x; sNg[nl][ko + 1] = nv.y; sNg[nl][ko + 2] = nv.z; sNg[nl][ko + 3] = nv.w;
        }
        // load W tiles: 16 x 128 each (2 float4 / thread / tensor)
#pragma unroll
        for (int r = 0; r < 2; r++) {
            int i = tid + r * 256;          // 0..511
            int kr = i >> 5;                // 0..15
            int c4 = (i & 31) * 4;
            *(float4*)&sWs[kr][c4] = *(const float4*)(Wself + (size_t)(k0 + kr) * HH + c4);
            *(float4*)&sWn[kr][c4] = *(const float4*)(Wneigh + (size_t)(k0 + kr) * HH + c4);
        }
        __syncthreads();

#pragma unroll
        for (int kk = 0; kk < 16; kk++) {
            float4 ws = *(float4*)&sWs[kk][4 * lane];
            float4 wn = *(float4*)&sWn[kk][4 * lane];
#pragma unroll
            for (int i = 0; i < 8; i++) {
                float xv = sX[warp * 8 + i][kk];    // broadcast
                float nv = sNg[warp * 8 + i][kk];   // broadcast
                acc[i][0] += xv * ws.x + nv * wn.x;
                acc[i][1] += xv * ws.y + nv * wn.y;
                acc[i][2] += xv * ws.z + nv * wn.z;
                acc[i][3] += xv * ws.w + nv * wn.w;
            }
        }
        __syncthreads();
    }

    // epilogue: bias, store, BN partial sums
    float4 bv = *(const float4*)(bself + 4 * lane);
    float ps[4] = {0, 0, 0, 0}, pq[4] = {0, 0, 0, 0};
#pragma unroll
    for (int i = 0; i < 8; i++) {
        int gn = n0 + warp * 8 + i;
        if (gn < NN) {
            float4 o;
            o.x = acc[i][0] + bv.x; o.y = acc[i][1] + bv.y;
            o.z = acc[i][2] + bv.z; o.w = acc[i][3] + bv.w;
            *(float4*)(hout + (size_t)gn * HH + 4 * lane) = o;
            ps[0] += o.x; ps[1] += o.y; ps[2] += o.z; ps[3] += o.w;
            pq[0] += o.x * o.x; pq[1] += o.y * o.y; pq[2] += o.z * o.z; pq[3] += o.w * o.w;
        }
    }
    *(float4*)&sred[warp][4 * lane] = make_float4(ps[0], ps[1], ps[2], ps[3]);
    __syncthreads();
    if (tid < HH) {
        float t = 0.f;
#pragma unroll
        for (int w = 0; w < 8; w++) t += sred[w][tid];
        atomicAdd(&g_colsum[tid], t);
    }
    __syncthreads();
    *(float4*)&sred[warp][4 * lane] = make_float4(pq[0], pq[1], pq[2], pq[3]);
    __syncthreads();
    if (tid < HH) {
        float t = 0.f;
#pragma unroll
        for (int w = 0; w < 8; w++) t += sred[w][tid];
        atomicAdd(&g_colsq[tid], t);
    }
}

// ---------------- BN finalize: mu/var -> per-col scale/shift; reset accumulators ----------------
__global__ void k_bnfin(const float* __restrict__ gamma, const float* __restrict__ beta) {
    int t = threadIdx.x;  // 128 threads
    float s = g_colsum[t], q = g_colsq[t];
    const float invn = 1.0f / (float)NN;
    float mu = s * invn;
    float var = fmaxf(q * invn - mu * mu, 0.f);
    float r = rsqrtf(var + EPSBN);
    float sc = r * gamma[t];
    g_scale[t] = sc;
    g_shift[t] = beta[t] - mu * sc;
    g_colsum[t] = 0.f;
    g_colsq[t] = 0.f;
}

// ---------------- normalize + ReLU (in place), float4 ----------------
__global__ void k_norm(float* __restrict__ h) {
    size_t i = (size_t)blockIdx.x * blockDim.x + threadIdx.x;  // float4 index
    if (i >= (size_t)NN * HH / 4) return;
    int c4 = ((int)(i & 31)) * 4;
    float4 v = ((float4*)h)[i];
    float4 sc = *(float4*)&g_scale[c4];
    float4 sh = *(float4*)&g_shift[c4];
    v.x = fmaxf(fmaf(v.x, sc.x, sh.x), 0.f);
    v.y = fmaxf(fmaf(v.y, sc.y, sh.y), 0.f);
    v.z = fmaxf(fmaf(v.z, sc.z, sh.z), 0.f);
    v.w = fmaxf(fmaf(v.w, sc.w, sh.w), 0.f);
    ((float4*)h)[i] = v;
}

// ---------------- classifier: warp per node, out[n, 0:2] = h[n,:] @ Wc + bc ----------------
__global__ void k_cls(const float* __restrict__ h, const float* __restrict__ Wc,
                      const float* __restrict__ bc, float* __restrict__ out) {
    int gw = (blockIdx.x * blockDim.x + threadIdx.x) >> 5;
    int lane = threadIdx.x & 31;
    if (gw >= NN) return;
    float4 v = *(const float4*)(h + (size_t)gw * HH + 4 * lane);
    int k = 4 * lane;
    float a0 = v.x * __ldg(&Wc[(k + 0) * 2]) + v.y * __ldg(&Wc[(k + 1) * 2]) +
               v.z * __ldg(&Wc[(k + 2) * 2]) + v.w * __ldg(&Wc[(k + 3) * 2]);
    float a1 = v.x * __ldg(&Wc[(k + 0) * 2 + 1]) + v.y * __ldg(&Wc[(k + 1) * 2 + 1]) +
               v.z * __ldg(&Wc[(k + 2) * 2 + 1]) + v.w * __ldg(&Wc[(k + 3) * 2 + 1]);
#pragma unroll
    for (int o = 16; o; o >>= 1) {
        a0 += __shfl_xor_sync(0xFFFFFFFFu, a0, o);
        a1 += __shfl_xor_sync(0xFFFFFFFFu, a1, o);
    }
    if (lane == 0) {
        out[(size_t)gw * 2 + 0] = a0 + __ldg(&bc[0]);
        out[(size_t)gw * 2 + 1] = a1 + __ldg(&bc[1]);
    }
}

// ---------------- launch ----------------
extern "C" void kernel_launch(void* const* d_in, const int* in_sizes, int n_in,
                              void* d_out, int out_size) {
    const float* x   = (const float*)d_in[0];
    const int*   src = (const int*)d_in[1];
    const int*   dst = (const int*)d_in[2];
    const float* Ws0 = (const float*)d_in[3];
    const float* bs0 = (const float*)d_in[4];
    const float* Wn0 = (const float*)d_in[5];
    const float* ga0 = (const float*)d_in[6];
    const float* be0 = (const float*)d_in[7];
    const float* Ws1 = (const float*)d_in[8];
    const float* bs1 = (const float*)d_in[9];
    const float* Wn1 = (const float*)d_in[10];
    const float* ga1 = (const float*)d_in[11];
    const float* be1 = (const float*)d_in[12];
    const float* Ws2 = (const float*)d_in[13];
    const float* bs2 = (const float*)d_in[14];
    const float* Wn2 = (const float*)d_in[15];
    const float* ga2 = (const float*)d_in[16];
    const float* be2 = (const float*)d_in[17];
    const float* Wc  = (const float*)d_in[18];
    const float* bc  = (const float*)d_in[19];
    float* out = (float*)d_out;

    void* p;
    cudaGetSymbolAddress(&p, g_h0);  float* h0 = (float*)p;
    cudaGetSymbolAddress(&p, g_h1);  float* h1 = (float*)p;

    const int TB = 256;
    // graph structure (rebuilt each call; graph-capture safe, no allocations)
    k_init<<<(NN + TB - 1) / TB, TB>>>();
    k_hist<<<(EE + TB - 1) / TB, TB>>>(dst);
    k_scan1<<<NB_SCAN, SCAN_B>>>();
    k_scan2<<<1, 128>>>();
    k_scan3<<<NB_SCAN, SCAN_B>>>();
    k_fill<<<(EE + TB - 1) / TB, TB>>>(src, dst);

    const int AGG_BLK = (NN * 32 + TB - 1) / TB;   // warp per node
    const int GEMM_BLK = (NN + 63) / 64;
    const int NORM_BLK = ((NN * HH / 4) + TB - 1) / TB;

    // layer 0: Din = 64
    k_agg<64><<<AGG_BLK, TB>>>(x);
    k_gemm<64><<<GEMM_BLK, TB>>>(x, Ws0, Wn0, bs0, h0);
    k_bnfin<<<1, 128>>>(ga0, be0);
    k_norm<<<NORM_BLK, TB>>>(h0);

    // layer 1: Din = 128
    k_agg<128><<<AGG_BLK, TB>>>(h0);
    k_gemm<128><<<GEMM_BLK, TB>>>(h0, Ws1, Wn1, bs1, h1);
    k_bnfin<<<1, 128>>>(ga1, be1);
    k_norm<<<NORM_BLK, TB>>>(h1);

    // layer 2: Din = 128
    k_agg<128><<<AGG_BLK, TB>>>(h1);
    k_gemm<128><<<GEMM_BLK, TB>>>(h1, Ws2, Wn2, bs2, h0);
    k_bnfin<<<1, 128>>>(ga2, be2);
    k_norm<<<NORM_BLK, TB>>>(h0);

    k_cls<<<AGG_BLK, TB>>>(h0, Wc, bc, out);
}

// round 2
// speedup vs baseline: 2.0456x; 2.0456x over previous
#include <cuda_runtime.h>
#include <cstdint>

#define NN 100000
#define EE 1250000
#define HH 128
#define EPSBN 1e-5f
#define SCAN_B 1024
#define NB_SCAN ((NN + SCAN_B - 1) / SCAN_B)   // 98

typedef unsigned long long ull;

__device__ __forceinline__ ull pack2(float a, float b) {
    ull r; asm("mov.b64 %0, {%1, %2};" : "=l"(r) : "f"(a), "f"(b)); return r;
}
__device__ __forceinline__ void unpack2(ull a, float& x, float& y) {
    asm("mov.b64 {%0, %1}, %2;" : "=f"(x), "=f"(y) : "l"(a));
}
__device__ __forceinline__ ull fma2(ull a, ull b, ull c) {
    ull d; asm("fma.rn.f32x2 %0, %1, %2, %3;" : "=l"(d) : "l"(a), "l"(b), "l"(c)); return d;
}

// ---------------- static device scratch ----------------
__device__ int g_deg[NN];
__device__ int g_rowptr[NN + 1];
__device__ int g_fill[NN];
__device__ int g_csr[EE];
__device__ int g_bsums[NB_SCAN];
__device__ __align__(16) float g_neigh[(size_t)NN * HH];
__device__ __align__(16) float g_h0[(size_t)NN * HH];
__device__ __align__(16) float g_h1[(size_t)NN * HH];
__device__ __align__(16) float g_colsum[HH];
__device__ __align__(16) float g_colsq[HH];
__device__ __align__(16) float g_scale[HH];
__device__ __align__(16) float g_shift[HH];

// ---------------- init ----------------
__global__ void k_init() {
    int i = blockIdx.x * blockDim.x + threadIdx.x;
    if (i < NN) { g_deg[i] = 0; g_fill[i] = 0; }
    if (i < HH) { g_colsum[i] = 0.f; g_colsq[i] = 0.f; }
}

// ---------------- CSR build ----------------
__global__ void k_hist(const int* __restrict__ dst) {
    int e = blockIdx.x * blockDim.x + threadIdx.x;
    if (e < EE) atomicAdd(&g_deg[dst[e]], 1);
}

__global__ void k_scan1() {
    __shared__ int s[SCAN_B];
    int tid = threadIdx.x;
    int i = blockIdx.x * SCAN_B + tid;
    int v = (i < NN) ? g_deg[i] : 0;
    s[tid] = v;
    __syncthreads();
    for (int off = 1; off < SCAN_B; off <<= 1) {
        int t = (tid >= off) ? s[tid - off] : 0;
        __syncthreads();
        s[tid] += t;
        __syncthreads();
    }
    if (i < NN) g_rowptr[i] = s[tid] - v;
    if (tid == SCAN_B - 1) g_bsums[blockIdx.x] = s[tid];
}

__global__ void k_scan2() {
    __shared__ int s[128];
    int tid = threadIdx.x;
    int v = (tid < NB_SCAN) ? g_bsums[tid] : 0;
    s[tid] = v;
    __syncthreads();
    for (int off = 1; off < 128; off <<= 1) {
        int t = (tid >= off) ? s[tid - off] : 0;
        __syncthreads();
        s[tid] += t;
        __syncthreads();
    }
    if (tid < NB_SCAN) g_bsums[tid] = s[tid] - v;
    if (tid == 127) g_rowptr[NN] = s[127];
}

__global__ void k_scan3() {
    int i = blockIdx.x * SCAN_B + threadIdx.x;
    if (i < NN) g_rowptr[i] += g_bsums[blockIdx.x];
}

__global__ void k_fill(const int* __restrict__ src, const int* __restrict__ dst) {
    int e = blockIdx.x * blockDim.x + threadIdx.x;
    if (e < EE) {
        int d = dst[e];
        int p = atomicAdd(&g_fill[d], 1);
        g_csr[g_rowptr[d] + p] = src[e];
    }
}

// ---------------- mean aggregation (warp/node); optional fused BN+ReLU on loads ----------------
template <int DIN, bool APPLY>
__global__ void k_agg(const float* __restrict__ xin) {
    int gw = (blockIdx.x * blockDim.x + threadIdx.x) >> 5;
    int lane = threadIdx.x & 31;
    if (gw >= NN) return;
    const int R = DIN / 32;
    float sc[R], sh[R];
    if (APPLY) {
#pragma unroll
        for (int j = 0; j < R; j++) { sc[j] = g_scale[lane + 32 * j]; sh[j] = g_shift[lane + 32 * j]; }
    }
    int beg = g_rowptr[gw], end = g_rowptr[gw + 1];
    float acc[R];
#pragma unroll
    for (int j = 0; j < R; j++) acc[j] = 0.f;
#pragma unroll 2
    for (int e = beg; e < end; e++) {
        int s = g_csr[e];
        const float* row = xin + (size_t)s * DIN;
#pragma unroll
        for (int j = 0; j < R; j++) {
            float v = __ldg(row + lane + 32 * j);
            if (APPLY) v = fmaxf(fmaf(v, sc[j], sh[j]), 0.f);
            acc[j] += v;
        }
    }
    float inv = (end > beg) ? 1.0f / (float)(end - beg) : 0.f;
    float* o = g_neigh + (size_t)gw * DIN;
#pragma unroll
    for (int j = 0; j < R; j++) o[lane + 32 * j] = acc[j] * inv;
}

// ---------------- fused dual-GEMM (FFMA2) + bias + BN-stat partials ----------------
// h[n,:] = act(x[n,:]) @ Wself + neigh[n,:] @ Wneigh + b   where act = BN+ReLU if APPLY.
// 256 threads, 64 nodes/block; f32x2 accumulators pack node pairs.
#define XPAD 66
template <int DIN, bool APPLY>
__launch_bounds__(256)
__global__ void k_gemm(const float* __restrict__ x,
                       const float* __restrict__ Wself,
                       const float* __restrict__ Wneigh,
                       const float* __restrict__ bself,
                       float* __restrict__ hout) {
    __shared__ float sXt[16][XPAD];   // transposed: [k][node]
    __shared__ float sNt[16][XPAD];
    __shared__ float sWs[16][HH];
    __shared__ float sWn[16][HH];
    __shared__ float sred[8][HH];

    const int tid = threadIdx.x;
    const int warp = tid >> 5, lane = tid & 31;
    const int n0 = blockIdx.x * 64;

    ull acc[4][4];
#pragma unroll
    for (int p = 0; p < 4; p++)
#pragma unroll
        for (int c = 0; c < 4; c++) acc[p][c] = 0ull;

    for (int k0 = 0; k0 < DIN; k0 += 16) {
        // activation tiles (transposed stores, normalized x if APPLY)
        {
            int nl = tid >> 2;
            int ko = (tid & 3) * 4;
            int gn = min(n0 + nl, NN - 1);
            float4 xv = *(const float4*)(x + (size_t)gn * DIN + k0 + ko);
            float4 nv = *(const float4*)(g_neigh + (size_t)gn * DIN + k0 + ko);
            if (APPLY) {
                float4 sc = *(const float4*)&g_scale[k0 + ko];
                float4 shf = *(const float4*)&g_shift[k0 + ko];
                xv.x = fmaxf(fmaf(xv.x, sc.x, shf.x), 0.f);
                xv.y = fmaxf(fmaf(xv.y, sc.y, shf.y), 0.f);
                xv.z = fmaxf(fmaf(xv.z, sc.z, shf.z), 0.f);
                xv.w = fmaxf(fmaf(xv.w, sc.w, shf.w), 0.f);
            }
            sXt[ko + 0][nl] = xv.x; sXt[ko + 1][nl] = xv.y;
            sXt[ko + 2][nl] = xv.z; sXt[ko + 3][nl] = xv.w;
            sNt[ko + 0][nl] = nv.x; sNt[ko + 1][nl] = nv.y;
            sNt[ko + 2][nl] = nv.z; sNt[ko + 3][nl] = nv.w;
        }
        // weight tiles 16 x 128 each
#pragma unroll
        for (int r = 0; r < 2; r++) {
            int i = tid + r * 256;
            int kr = i >> 5;
            int c4 = (i & 31) * 4;
            *(float4*)&sWs[kr][c4] = *(const float4*)(Wself + (size_t)(k0 + kr) * HH + c4);
            *(float4*)&sWn[kr][c4] = *(const float4*)(Wneigh + (size_t)(k0 + kr) * HH + c4);
        }
        __syncthreads();

#pragma unroll
        for (int kk = 0; kk < 16; kk++) {
            float4 ws = *(float4*)&sWs[kk][4 * lane];
            float4 wn = *(float4*)&sWn[kk][4 * lane];
            ull wsp[4] = {pack2(ws.x, ws.x), pack2(ws.y, ws.y), pack2(ws.z, ws.z), pack2(ws.w, ws.w)};
            ull wnp[4] = {pack2(wn.x, wn.x), pack2(wn.y, wn.y), pack2(wn.z, wn.z), pack2(wn.w, wn.w)};
            const ull* xr = (const ull*)&sXt[kk][warp * 8];   // broadcast node-pair loads
            const ull* nr = (const ull*)&sNt[kk][warp * 8];
#pragma unroll
            for (int p = 0; p < 4; p++) {
                ull xp = xr[p], np = nr[p];
#pragma unroll
                for (int c = 0; c < 4; c++) {
                    acc[p][c] = fma2(xp, wsp[c], acc[p][c]);
                    acc[p][c] = fma2(np, wnp[c], acc[p][c]);
                }
            }
        }
        __syncthreads();
    }

    // epilogue: unpack, bias, store, BN partials
    float4 bv = *(const float4*)(bself + 4 * lane);
    float ps[4] = {0, 0, 0, 0}, pq[4] = {0, 0, 0, 0};
#pragma unroll
    for (int p = 0; p < 4; p++) {
        float o0[4], o1[4];
#pragma unroll
        for (int c = 0; c < 4; c++) unpack2(acc[p][c], o0[c], o1[c]);
        int gn = n0 + warp * 8 + 2 * p;
        if (gn < NN) {
            float4 o;
            o.x = o0[0] + bv.x; o.y = o0[1] + bv.y; o.z = o0[2] + bv.z; o.w = o0[3] + bv.w;
            *(float4*)(hout + (size_t)gn * HH + 4 * lane) = o;
            ps[0] += o.x; ps[1] += o.y; ps[2] += o.z; ps[3] += o.w;
            pq[0] += o.x * o.x; pq[1] += o.y * o.y; pq[2] += o.z * o.z; pq[3] += o.w * o.w;
        }
        if (gn + 1 < NN) {
            float4 o;
            o.x = o1[0] + bv.x; o.y = o1[1] + bv.y; o.z = o1[2] + bv.z; o.w = o1[3] + bv.w;
            *(float4*)(hout + (size_t)(gn + 1) * HH + 4 * lane) = o;
            ps[0] += o.x; ps[1] += o.y; ps[2] += o.z; ps[3] += o.w;
            pq[0] += o.x * o.x; pq[1] += o.y * o.y; pq[2] += o.z * o.z; pq[3] += o.w * o.w;
        }
    }
    *(float4*)&sred[warp][4 * lane] = make_float4(ps[0], ps[1], ps[2], ps[3]);
    __syncthreads();
    if (tid < HH) {
        float t = 0.f;
#pragma unroll
        for (int w = 0; w < 8; w++) t += sred[w][tid];
        atomicAdd(&g_colsum[tid], t);
    }
    __syncthreads();
    *(float4*)&sred[warp][4 * lane] = make_float4(pq[0], pq[1], pq[2], pq[3]);
    __syncthreads();
    if (tid < HH) {
        float t = 0.f;
#pragma unroll
        for (int w = 0; w < 8; w++) t += sred[w][tid];
        atomicAdd(&g_colsq[tid], t);
    }
}

// ---------------- BN finalize ----------------
__global__ void k_bnfin(const float* __restrict__ gamma, const float* __restrict__ beta) {
    int t = threadIdx.x;  // 128 threads
    float s = g_colsum[t], q = g_colsq[t];
    const float invn = 1.0f / (float)NN;
    float mu = s * invn;
    float var = fmaxf(q * invn - mu * mu, 0.f);
    float r = rsqrtf(var + EPSBN);
    float sc = r * gamma[t];
    g_scale[t] = sc;
    g_shift[t] = beta[t] - mu * sc;
    g_colsum[t] = 0.f;
    g_colsq[t] = 0.f;
}

// ---------------- classifier: fused BN+ReLU, warp per node ----------------
__global__ void k_cls(const float* __restrict__ h, const float* __restrict__ Wc,
                      const float* __restrict__ bc, float* __restrict__ out) {
    int gw = (blockIdx.x * blockDim.x + threadIdx.x) >> 5;
    int lane = threadIdx.x & 31;
    if (gw >= NN) return;
    float4 v = *(const float4*)(h + (size_t)gw * HH + 4 * lane);
    float4 sc = *(const float4*)&g_scale[4 * lane];
    float4 shf = *(const float4*)&g_shift[4 * lane];
    v.x = fmaxf(fmaf(v.x, sc.x, shf.x), 0.f);
    v.y = fmaxf(fmaf(v.y, sc.y, shf.y), 0.f);
    v.z = fmaxf(fmaf(v.z, sc.z, shf.z), 0.f);
    v.w = fmaxf(fmaf(v.w, sc.w, shf.w), 0.f);
    int k = 4 * lane;
    float a0 = v.x * __ldg(&Wc[(k + 0) * 2]) + v.y * __ldg(&Wc[(k + 1) * 2]) +
               v.z * __ldg(&Wc[(k + 2) * 2]) + v.w * __ldg(&Wc[(k + 3) * 2]);
    float a1 = v.x * __ldg(&Wc[(k + 0) * 2 + 1]) + v.y * __ldg(&Wc[(k + 1) * 2 + 1]) +
               v.z * __ldg(&Wc[(k + 2) * 2 + 1]) + v.w * __ldg(&Wc[(k + 3) * 2 + 1]);
#pragma unroll
    for (int o = 16; o; o >>= 1) {
        a0 += __shfl_xor_sync(0xFFFFFFFFu, a0, o);
        a1 += __shfl_xor_sync(0xFFFFFFFFu, a1, o);
    }
    if (lane == 0) {
        out[(size_t)gw * 2 + 0] = a0 + __ldg(&bc[0]);
        out[(size_t)gw * 2 + 1] = a1 + __ldg(&bc[1]);
    }
}

// ---------------- launch ----------------
extern "C" void kernel_launch(void* const* d_in, const int* in_sizes, int n_in,
                              void* d_out, int out_size) {
    const float* x   = (const float*)d_in[0];
    const int*   src = (const int*)d_in[1];
    const int*   dst = (const int*)d_in[2];
    const float* Ws0 = (const float*)d_in[3];
    const float* bs0 = (const float*)d_in[4];
    const float* Wn0 = (const float*)d_in[5];
    const float* ga0 = (const float*)d_in[6];
    const float* be0 = (const float*)d_in[7];
    const float* Ws1 = (const float*)d_in[8];
    const float* bs1 = (const float*)d_in[9];
    const float* Wn1 = (const float*)d_in[10];
    const float* ga1 = (const float*)d_in[11];
    const float* be1 = (const float*)d_in[12];
    const float* Ws2 = (const float*)d_in[13];
    const float* bs2 = (const float*)d_in[14];
    const float* Wn2 = (const float*)d_in[15];
    const float* ga2 = (const float*)d_in[16];
    const float* be2 = (const float*)d_in[17];
    const float* Wc  = (const float*)d_in[18];
    const float* bc  = (const float*)d_in[19];
    float* out = (float*)d_out;

    void* p;
    cudaGetSymbolAddress(&p, g_h0);  float* h0 = (float*)p;
    cudaGetSymbolAddress(&p, g_h1);  float* h1 = (float*)p;

    const int TB = 256;
    k_init<<<(NN + TB - 1) / TB, TB>>>();
    k_hist<<<(EE + TB - 1) / TB, TB>>>(dst);
    k_scan1<<<NB_SCAN, SCAN_B>>>();
    k_scan2<<<1, 128>>>();
    k_scan3<<<NB_SCAN, SCAN_B>>>();
    k_fill<<<(EE + TB - 1) / TB, TB>>>(src, dst);

    const int AGG_BLK = (NN * 32 + TB - 1) / TB;
    const int GEMM_BLK = (NN + 63) / 64;

    // layer 0 (Din=64, raw input)
    k_agg<64, false><<<AGG_BLK, TB>>>(x);
    k_gemm<64, false><<<GEMM_BLK, TB>>>(x, Ws0, Wn0, bs0, h0);
    k_bnfin<<<1, 128>>>(ga0, be0);

    // layer 1 (Din=128, fused BN0+ReLU on h0 loads)
    k_agg<128, true><<<AGG_BLK, TB>>>(h0);
    k_gemm<128, true><<<GEMM_BLK, TB>>>(h0, Ws1, Wn1, bs1, h1);
    k_bnfin<<<1, 128>>>(ga1, be1);

    // layer 2 (Din=128, fused BN1+ReLU on h1 loads)
    k_agg<128, true><<<AGG_BLK, TB>>>(h1);
    k_gemm<128, true><<<GEMM_BLK, TB>>>(h1, Ws2, Wn2, bs2, h0);
    k_bnfin<<<1, 128>>>(ga2, be2);

    // classifier (fused BN2+ReLU)
    k_cls<<<AGG_BLK, TB>>>(h0, Wc, bc, out);
}

// round 4
// speedup vs baseline: 3.1056x; 1.5182x over previous
#include <cuda_runtime.h>
#include <cuda_fp16.h>
#include <cstdint>

#define NN 100000
#define EE 1250000
#define HH 128
#define EPSBN 1e-5f
#define SCAN_B 1024
#define NB_SCAN ((NN + SCAN_B - 1) / SCAN_B)   // 98
#define KC 64

// ---------------- static device scratch ----------------
__device__ int g_deg[NN];
__device__ int g_rowptr[NN + 1];
__device__ int g_fill[NN];
__device__ int g_csr[EE];
__device__ int g_bsums[NB_SCAN];
__device__ __align__(16) __half g_xf16[(size_t)NN * 64];
__device__ __align__(16) __half g_a16[(size_t)NN * HH];
__device__ __align__(16) __half g_b16[(size_t)NN * HH];
__device__ __align__(16) __half g_ng16[(size_t)NN * HH];
__device__ __align__(16) float  g_h32[(size_t)NN * HH];
__device__ __align__(16) __half g_wT0[HH * 128];
__device__ __align__(16) __half g_wT1[HH * 256];
__device__ __align__(16) __half g_wT2[HH * 256];
__device__ __align__(16) float g_colsum[HH];
__device__ __align__(16) float g_colsq[HH];
__device__ __align__(16) float g_scale[HH];
__device__ __align__(16) float g_shift[HH];

// ---------------- PTX helpers (non-'a' ISA only) ----------------
__device__ __forceinline__ uint32_t smem_u32(const void* p) {
    uint32_t a;
    asm("{ .reg .u64 t; cvta.to.shared.u64 t, %1; cvt.u32.u64 %0, t; }" : "=r"(a) : "l"(p));
    return a;
}
__device__ __forceinline__ void ldsm4(uint32_t* r, uint32_t addr) {
    asm volatile("ldmatrix.sync.aligned.m8n8.x4.shared.b16 {%0,%1,%2,%3}, [%4];"
                 : "=r"(r[0]), "=r"(r[1]), "=r"(r[2]), "=r"(r[3]) : "r"(addr));
}
__device__ __forceinline__ void mma16816(float* d, const uint32_t* a, const uint32_t* b) {
    asm volatile("mma.sync.aligned.m16n8k16.row.col.f32.f16.f16.f32 "
                 "{%0,%1,%2,%3}, {%4,%5,%6,%7}, {%8,%9}, {%0,%1,%2,%3};"
                 : "+f"(d[0]), "+f"(d[1]), "+f"(d[2]), "+f"(d[3])
                 : "r"(a[0]), "r"(a[1]), "r"(a[2]), "r"(a[3]), "r"(b[0]), "r"(b[1]));
}

// ---------------- init ----------------
__global__ void k_init() {
    int i = blockIdx.x * blockDim.x + threadIdx.x;
    if (i < NN) { g_deg[i] = 0; g_fill[i] = 0; }
    if (i < HH) { g_colsum[i] = 0.f; g_colsq[i] = 0.f; }
}

// ---------------- CSR build ----------------
__global__ void k_hist(const int* __restrict__ dst) {
    int e = blockIdx.x * blockDim.x + threadIdx.x;
    if (e < EE) atomicAdd(&g_deg[dst[e]], 1);
}

__global__ void k_scan1() {
    __shared__ int s[SCAN_B];
    int tid = threadIdx.x;
    int i = blockIdx.x * SCAN_B + tid;
    int v = (i < NN) ? g_deg[i] : 0;
    s[tid] = v;
    __syncthreads();
    for (int off = 1; off < SCAN_B; off <<= 1) {
        int t = (tid >= off) ? s[tid - off] : 0;
        __syncthreads();
        s[tid] += t;
        __syncthreads();
    }
    if (i < NN) g_rowptr[i] = s[tid] - v;
    if (tid == SCAN_B - 1) g_bsums[blockIdx.x] = s[tid];
}

__global__ void k_scan2() {
    __shared__ int s[128];
    int tid = threadIdx.x;
    int v = (tid < NB_SCAN) ? g_bsums[tid] : 0;
    s[tid] = v;
    __syncthreads();
    for (int off = 1; off < 128; off <<= 1) {
        int t = (tid >= off) ? s[tid - off] : 0;
        __syncthreads();
        s[tid] += t;
        __syncthreads();
    }
    if (tid < NB_SCAN) g_bsums[tid] = s[tid] - v;
    if (tid == 127) g_rowptr[NN] = s[127];
}

__global__ void k_scan3() {
    int i = blockIdx.x * SCAN_B + threadIdx.x;
    if (i < NN) g_rowptr[i] += g_bsums[blockIdx.x];
}

__global__ void k_fill(const int* __restrict__ src, const int* __restrict__ dst) {
    int e = blockIdx.x * blockDim.x + threadIdx.x;
    if (e < EE) {
        int d = dst[e];
        int p = atomicAdd(&g_fill[d], 1);
        g_csr[g_rowptr[d] + p] = src[e];
    }
}

// ---------------- converts ----------------
__global__ void k_cvtx(const float* __restrict__ x) {     // x fp32 -> fp16
    size_t i = (size_t)blockIdx.x * blockDim.x + threadIdx.x;
    if (i >= (size_t)NN * 64 / 2) return;
    float2 v = ((const float2*)x)[i];
    ((__half2*)g_xf16)[i] = __floats2half2_rn(v.x, v.y);
}

__global__ void k_cvt(const float* __restrict__ h, __half* __restrict__ o) {  // BN+ReLU -> fp16
    size_t i = (size_t)blockIdx.x * blockDim.x + threadIdx.x;
    if (i >= (size_t)NN * HH / 2) return;
    int c2 = ((int)(i & 63)) * 2;
    float2 v = ((const float2*)h)[i];
    float2 sc = *(const float2*)&g_scale[c2];
    float2 sh = *(const float2*)&g_shift[c2];
    float a = fmaxf(fmaf(v.x, sc.x, sh.x), 0.f);
    float b = fmaxf(fmaf(v.y, sc.y, sh.y), 0.f);
    ((__half2*)o)[i] = __floats2half2_rn(a, b);
}

// build combined transposed weights: o[n][k0+k] = W[k][n]
__global__ void k_prepw(const float* __restrict__ W, __half* __restrict__ o,
                        int KTOT, int DIN, int k0) {
    int i = blockIdx.x * blockDim.x + threadIdx.x;
    if (i >= HH * DIN) return;
    int k = i / HH, n = i % HH;
    o[(size_t)n * KTOT + k0 + k] = __float2half(W[(size_t)k * HH + n]);
}

// ---------------- mean aggregation (warp/node), fp16 in/out ----------------
template <int DIN>
__global__ void k_agg16(const __half* __restrict__ xin) {
    int gw = (blockIdx.x * blockDim.x + threadIdx.x) >> 5;
    int lane = threadIdx.x & 31;
    if (gw >= NN) return;
    int beg = g_rowptr[gw], end = g_rowptr[gw + 1];
    const int R = DIN / 64;   // half2 per lane
    float2 acc[R];
#pragma unroll
    for (int j = 0; j < R; j++) acc[j] = make_float2(0.f, 0.f);
#pragma unroll 2
    for (int e = beg; e < end; e++) {
        const __half2* row = (const __half2*)(xin + (size_t)g_csr[e] * DIN);
#pragma unroll
        for (int j = 0; j < R; j++) {
            float2 f = __half22float2(__ldg(row + lane + 32 * j));
            acc[j].x += f.x; acc[j].y += f.y;
        }
    }
    float inv = (end > beg) ? 1.0f / (float)(end - beg) : 0.f;
    __half2* o = (__half2*)(g_ng16 + (size_t)gw * DIN);
#pragma unroll
    for (int j = 0; j < R; j++) o[lane + 32 * j] = __floats2half2_rn(acc[j].x * inv, acc[j].y * inv);
}

// ---------------- HMMA GEMM: h[128 tile][128] = [X|Ng] @ wT' + bias ----------------
// 256 thr = 8 warps (4m x 2n); warp tile 32x64 = 2x8 m16n8k16 atoms.
template <int KTOT>
__launch_bounds__(256, 2)
__global__ void k_gemm_hmma(const __half* __restrict__ xf, const __half* __restrict__ ngf,
                            const __half* __restrict__ wT, const float* __restrict__ bias,
                            float* __restrict__ hout) {
    const int DIN = KTOT / 2;
    __shared__ __half sA[128][KC + 8];
    __shared__ __half sB[128][KC + 8];
    __shared__ float sbias[HH];

    int tid = threadIdx.x, lane = tid & 31, wid = tid >> 5;
    int wm = wid & 3, wn = wid >> 2;
    int n0 = blockIdx.x * 128;
    if (tid < HH) sbias[tid] = bias[tid];

    float acc[2][8][4];
#pragma unroll
    for (int am = 0; am < 2; am++)
#pragma unroll
        for (int an = 0; an < 8; an++)
#pragma unroll
            for (int j = 0; j < 4; j++) acc[am][an][j] = 0.f;

    // per-lane ldmatrix source coordinates
    int aRow = wm * 32 + (lane & 15);
    int aCol = (lane >> 4) * 8;
    int bRow = wn * 64 + ((lane >> 4) << 3) + (lane & 7);
    int bCol = ((lane >> 3) & 1) * 8;

    for (int ch = 0; ch < KTOT / KC; ch++) {
        int kc0 = ch * KC;
        const __half* asrc = (kc0 < DIN) ? (xf + kc0) : (ngf + (kc0 - DIN));
        for (int i = tid; i < 128 * 8; i += 256) {
            int row = i >> 3, c8 = (i & 7) * 8;
            int gn = min(n0 + row, NN - 1);
            *(uint4*)&sA[row][c8] = *(const uint4*)(asrc + (size_t)gn * DIN + c8);
            *(uint4*)&sB[row][c8] = *(const uint4*)(wT + (size_t)row * KTOT + kc0 + c8);
        }
        __syncthreads();
#pragma unroll
        for (int kk = 0; kk < KC; kk += 16) {
            uint32_t a[2][4];
#pragma unroll
            for (int am = 0; am < 2; am++)
                ldsm4(a[am], smem_u32(&sA[aRow + am * 16][kk + aCol]));
            uint32_t b[8][2];
#pragma unroll
            for (int bi = 0; bi < 4; bi++) {
                uint32_t r[4];
                ldsm4(r, smem_u32(&sB[bRow + bi * 16][kk + bCol]));
                b[2 * bi][0] = r[0]; b[2 * bi][1] = r[1];
                b[2 * bi + 1][0] = r[2]; b[2 * bi + 1][1] = r[3];
            }
#pragma unroll
            for (int am = 0; am < 2; am++)
#pragma unroll
                for (int an = 0; an < 8; an++)
                    mma16816(acc[am][an], a[am], b[an]);
        }
        __syncthreads();
    }

    // epilogue: bias + store fp32
    int r0 = wm * 32 + (lane >> 2);
    int c0 = wn * 64 + (lane & 3) * 2;
#pragma unroll
    for (int am = 0; am < 2; am++) {
        int gr = n0 + r0 + am * 16;
#pragma unroll
        for (int an = 0; an < 8; an++) {
            int c = c0 + an * 8;
            if (gr < NN) {
                float2 v = make_float2(acc[am][an][0] + sbias[c], acc[am][an][1] + sbias[c + 1]);
                *(float2*)(hout + (size_t)gr * HH + c) = v;
            }
            if (gr + 8 < NN) {
                float2 v = make_float2(acc[am][an][2] + sbias[c], acc[am][an][3] + sbias[c + 1]);
                *(float2*)(hout + (size_t)(gr + 8) * HH + c) = v;
            }
        }
    }
}

// ---------------- BN column stats: 128 rows/block, float4 ----------------
__global__ void k_stats(const float* __restrict__ h) {
    __shared__ float4 ss[8][32], qq[8][32];
    int tid = threadIdx.x;
    int cg = tid & 31;          // 4-col group
    int rr = tid >> 5;          // 0..7
    int rend = min(blockIdx.x * 128 + 128, NN);
    float4 s = make_float4(0, 0, 0, 0), q = make_float4(0, 0, 0, 0);
    for (int r = blockIdx.x * 128 + rr; r < rend; r += 8) {
        float4 v = *(const float4*)(h + (size_t)r * HH + cg * 4);
        s.x += v.x; s.y += v.y; s.z += v.z; s.w += v.w;
        q.x += v.x * v.x; q.y += v.y * v.y; q.z += v.z * v.z; q.w += v.w * v.w;
    }
    ss[rr][cg] = s; qq[rr][cg] = q;
    __syncthreads();
    if (tid < 128) {
        float sa = 0.f, qa = 0.f;
#pragma unroll
        for (int k = 0; k < 8; k++) {
            sa += ((const float*)&ss[k][tid >> 2])[tid & 3];
            qa += ((const float*)&qq[k][tid >> 2])[tid & 3];
        }
        atomicAdd(&g_colsum[tid], sa);
        atomicAdd(&g_colsq[tid], qa);
    }
}

// ---------------- BN finalize ----------------
__global__ void k_bnfin(const float* __restrict__ gamma, const float* __restrict__ beta) {
    int t = threadIdx.x;  // 128
    float s = g_colsum[t], q = g_colsq[t];
    const float invn = 1.0f / (float)NN;
    float mu = s * invn;
    float var = fmaxf(q * invn - mu * mu, 0.f);
    float r = rsqrtf(var + EPSBN);
    float sc = r * gamma[t];
    g_scale[t] = sc;
    g_shift[t] = beta[t] - mu * sc;
    g_colsum[t] = 0.f;
    g_colsq[t] = 0.f;
}

// ---------------- classifier (reads normalized fp16) ----------------
__global__ void k_cls16(const __half* __restrict__ h, const float* __restrict__ Wc,
                        const float* __restrict__ bc, float* __restrict__ out) {
    int gw = (blockIdx.x * blockDim.x + threadIdx.x) >> 5;
    int lane = threadIdx.x & 31;
    if (gw >= NN) return;
    const __half2* row = (const __half2*)(h + (size_t)gw * HH);
    float a0 = 0.f, a1 = 0.f;
#pragma unroll
    for (int j = 0; j < 2; j++) {
        float2 f = __half22float2(__ldg(row + lane + 32 * j));
        int k = 2 * (lane + 32 * j);
        a0 += f.x * __ldg(&Wc[k * 2])     + f.y * __ldg(&Wc[(k + 1) * 2]);
        a1 += f.x * __ldg(&Wc[k * 2 + 1]) + f.y * __ldg(&Wc[(k + 1) * 2 + 1]);
    }
#pragma unroll
    for (int o = 16; o; o >>= 1) {
        a0 += __shfl_xor_sync(0xFFFFFFFFu, a0, o);
        a1 += __shfl_xor_sync(0xFFFFFFFFu, a1, o);
    }
    if (lane == 0) {
        out[(size_t)gw * 2 + 0] = a0 + __ldg(&bc[0]);
        out[(size_t)gw * 2 + 1] = a1 + __ldg(&bc[1]);
    }
}

// ---------------- launch ----------------
extern "C" void kernel_launch(void* const* d_in, const int* in_sizes, int n_in,
                              void* d_out, int out_size) {
    const float* x   = (const float*)d_in[0];
    const int*   src = (const int*)d_in[1];
    const int*   dst = (const int*)d_in[2];
    const float* Ws0 = (const float*)d_in[3];
    const float* bs0 = (const float*)d_in[4];
    const float* Wn0 = (const float*)d_in[5];
    const float* ga0 = (const float*)d_in[6];
    const float* be0 = (const float*)d_in[7];
    const float* Ws1 = (const float*)d_in[8];
    const float* bs1 = (const float*)d_in[9];
    const float* Wn1 = (const float*)d_in[10];
    const float* ga1 = (const float*)d_in[11];
    const float* be1 = (const float*)d_in[12];
    const float* Ws2 = (const float*)d_in[13];
    const float* bs2 = (const float*)d_in[14];
    const float* Wn2 = (const float*)d_in[15];
    const float* ga2 = (const float*)d_in[16];
    const float* be2 = (const float*)d_in[17];
    const float* Wc  = (const float*)d_in[18];
    const float* bc  = (const float*)d_in[19];
    float* out = (float*)d_out;

    void* p;
    cudaGetSymbolAddress(&p, g_xf16); __half* xf16 = (__half*)p;
    cudaGetSymbolAddress(&p, g_a16);  __half* a16  = (__half*)p;
    cudaGetSymbolAddress(&p, g_b16);  __half* b16  = (__half*)p;
    cudaGetSymbolAddress(&p, g_ng16); __half* ng16 = (__half*)p;
    cudaGetSymbolAddress(&p, g_h32);  float*  h32  = (float*)p;
    cudaGetSymbolAddress(&p, g_wT0);  __half* wT0  = (__half*)p;
    cudaGetSymbolAddress(&p, g_wT1);  __half* wT1  = (__half*)p;
    cudaGetSymbolAddress(&p, g_wT2);  __half* wT2  = (__half*)p;

    const int TB = 256;
    k_init<<<(NN + TB - 1) / TB, TB>>>();
    k_hist<<<(EE + TB - 1) / TB, TB>>>(dst);
    k_scan1<<<NB_SCAN, SCAN_B>>>();
    k_scan2<<<1, 128>>>();
    k_scan3<<<NB_SCAN, SCAN_B>>>();
    k_fill<<<(EE + TB - 1) / TB, TB>>>(src, dst);

    k_cvtx<<<(NN * 64 / 2 + TB - 1) / TB, TB>>>(x);
    const int PW64 = (HH * 64 + TB - 1) / TB, PW128 = (HH * HH + TB - 1) / TB;
    k_prepw<<<PW64, TB>>>(Ws0, wT0, 128, 64, 0);
    k_prepw<<<PW64, TB>>>(Wn0, wT0, 128, 64, 64);
    k_prepw<<<PW128, TB>>>(Ws1, wT1, 256, 128, 0);
    k_prepw<<<PW128, TB>>>(Wn1, wT1, 256, 128, 128);
    k_prepw<<<PW128, TB>>>(Ws2, wT2, 256, 128, 0);
    k_prepw<<<PW128, TB>>>(Wn2, wT2, 256, 128, 128);

    const int AGG_BLK  = (NN * 32 + TB - 1) / TB;
    const int GEMM_BLK = (NN + 127) / 128;       // 782
    const int CVT_BLK  = (NN * HH / 2 + TB - 1) / TB;

    // layer 0 (Din=64, K'=128)
    k_agg16<64><<<AGG_BLK, TB>>>(xf16);
    k_gemm_hmma<128><<<GEMM_BLK, TB>>>(xf16, ng16, wT0, bs0, h32);
    k_stats<<<GEMM_BLK, TB>>>(h32);
    k_bnfin<<<1, 128>>>(ga0, be0);
    k_cvt<<<CVT_BLK, TB>>>(h32, a16);

    // layer 1 (Din=128, K'=256)
    k_agg16<128><<<AGG_BLK, TB>>>(a16);
    k_gemm_hmma<256><<<GEMM_BLK, TB>>>(a16, ng16, wT1, bs1, h32);
    k_stats<<<GEMM_BLK, TB>>>(h32);
    k_bnfin<<<1, 128>>>(ga1, be1);
    k_cvt<<<CVT_BLK, TB>>>(h32, b16);

    // layer 2 (Din=128, K'=256)
    k_agg16<128><<<AGG_BLK, TB>>>(b16);
    k_gemm_hmma<256><<<GEMM_BLK, TB>>>(b16, ng16, wT2, bs2, h32);
    k_stats<<<GEMM_BLK, TB>>>(h32);
    k_bnfin<<<1, 128>>>(ga2, be2);
    k_cvt<<<CVT_BLK, TB>>>(h32, a16);

    // classifier
    k_cls16<<<AGG_BLK, TB>>>(a16, Wc, bc, out);
}